// round 17
// baseline (speedup 1.0000x reference)
#include <cuda_runtime.h>

// KernelNorm2d: kernel=2x2, stride=2, pad=0 -> identity spatial mapping.
// out[b,c,h,w] = (x[b,c,h,w] - mu[b,h/2,w/2]) * rsqrt(var[b,h/2,w/2] + eps)
// group = 64 channels x 2x2 pixels = 256 values per window.
//
// R16-confirmed design at the HBM mixed-R/W ceiling (6.33 TB/s), with the
// tile doubled: CTA = (batch, column-block, TWO consecutive row-pairs).
// Grid 4096, 256 threads, 16 float4/thread -> halves barriers and index
// setup per byte, 16 outstanding LDG.128 per thread (deeper DRAM queues).
// Thread t owns float4-col (t&15); segments seg = (t>>4) + 16*it
// (c = seg>>1, r = seg&1): each warp LDG/STG.128 covers 4 fully-dense
// 128B lines. Per row-pair, thread's 8 float4 span exactly 2 windows
// (A = x,y lanes; B = z,w lanes); one 8KB smem exchange + one barrier.
// __ldcs/__stcs: pure streaming. R12 lesson: no SHFL (MIO-path contention).

#define EPSV 1e-5f

__global__ __launch_bounds__(256, 2)
void knorm2d_kernel(const float* __restrict__ x, float* __restrict__ y) {
    const int bid  = blockIdx.x;
    const int ii   = bid & 63;         // row-quad index (rows 4*ii .. 4*ii+3)
    const int cblk = (bid >> 6) & 3;   // column block (16 float4-cols)
    const int b    = bid >> 8;         // batch
    const int t    = threadIdx.x;
    const int jloc = t & 15;           // float4-col within block
    const int s0   = t >> 4;           // starting segment 0..15

    const float4* __restrict__ xb = reinterpret_cast<const float4*>(x);
    float4* __restrict__ yb = reinterpret_cast<float4*>(y);

    const int j4 = (cblk << 4) | jloc;   // global float4-col 0..63
    const int chanStride4 = 256 * 64;    // 16384
    // row-pair rp in {0,1}: base index ((b*64 + c)*256 + 4*ii + 2*rp + r)*64 + j4
    const int base00 = (b * 64 * 256 + 4 * ii) * 64 + j4;   // rp=0
    const int base01 = base00 + 2 * 64;                     // rp=1

    float4 v[16];
#pragma unroll
    for (int it = 0; it < 8; ++it) {
        const int seg = s0 + (it << 4);                 // 0..127
        const int off = (seg >> 1) * chanStride4 + (seg & 1) * 64;
        v[it]     = __ldcs(xb + base00 + off);
        v[it + 8] = __ldcs(xb + base01 + off);
    }

    // Partial sums: per row-pair, window A = (x,y), window B = (z,w)
    float sA0 = 0.f, ssA0 = 0.f, sB0 = 0.f, ssB0 = 0.f;
    float sA1 = 0.f, ssA1 = 0.f, sB1 = 0.f, ssB1 = 0.f;
#pragma unroll
    for (int k = 0; k < 8; ++k) {
        const float4 q = v[k];
        sA0 += q.x + q.y;
        ssA0 = fmaf(q.x, q.x, fmaf(q.y, q.y, ssA0));
        sB0 += q.z + q.w;
        ssB0 = fmaf(q.z, q.z, fmaf(q.w, q.w, ssB0));
        const float4 p = v[k + 8];
        sA1 += p.x + p.y;
        ssA1 = fmaf(p.x, p.x, fmaf(p.y, p.y, ssA1));
        sB1 += p.z + p.w;
        ssB1 = fmaf(p.z, p.z, fmaf(p.w, p.w, ssB1));
    }

    // Exchange: the 16 threads with equal jloc share each window pair.
    __shared__ float4 red[2][256];
    red[0][t] = make_float4(sA0, ssA0, sB0, ssB0);
    red[1][t] = make_float4(sA1, ssA1, sB1, ssB1);
    __syncthreads();

    float SA0 = 0.f, SSA0 = 0.f, SB0 = 0.f, SSB0 = 0.f;
    float SA1 = 0.f, SSA1 = 0.f, SB1 = 0.f, SSB1 = 0.f;
#pragma unroll
    for (int k = 0; k < 16; ++k) {
        const float4 q = red[0][(k << 4) | jloc];
        SA0 += q.x; SSA0 += q.y; SB0 += q.z; SSB0 += q.w;
        const float4 p = red[1][(k << 4) | jloc];
        SA1 += p.x; SSA1 += p.y; SB1 += p.z; SSB1 += p.w;
    }

    const float inv = 1.0f / 256.0f;
    const float muA0 = SA0 * inv, muB0 = SB0 * inv;
    const float muA1 = SA1 * inv, muB1 = SB1 * inv;
    const float rA0 = rsqrtf(fmaf(-muA0, muA0, SSA0 * inv) + EPSV);
    const float rB0 = rsqrtf(fmaf(-muB0, muB0, SSB0 * inv) + EPSV);
    const float rA1 = rsqrtf(fmaf(-muA1, muA1, SSA1 * inv) + EPSV);
    const float rB1 = rsqrtf(fmaf(-muB1, muB1, SSB1 * inv) + EPSV);

#pragma unroll
    for (int it = 0; it < 8; ++it) {
        const int seg = s0 + (it << 4);
        const int off = (seg >> 1) * chanStride4 + (seg & 1) * 64;
        float4 q = v[it];
        q.x = (q.x - muA0) * rA0;
        q.y = (q.y - muA0) * rA0;
        q.z = (q.z - muB0) * rB0;
        q.w = (q.w - muB0) * rB0;
        __stcs(yb + base00 + off, q);
        float4 p = v[it + 8];
        p.x = (p.x - muA1) * rA1;
        p.y = (p.y - muA1) * rA1;
        p.z = (p.z - muB1) * rB1;
        p.w = (p.w - muB1) * rB1;
        __stcs(yb + base01 + off, p);
    }
}

extern "C" void kernel_launch(void* const* d_in, const int* in_sizes, int n_in,
                              void* d_out, int out_size) {
    const float* x = (const float*)d_in[0];
    float* y = (float*)d_out;
    knorm2d_kernel<<<16 * 64 * 4, 256>>>(x, y);
}